// round 4
// baseline (speedup 1.0000x reference)
#include <cuda_runtime.h>
#include <cuda_pipeline.h>
#include <cstdint>

#define N_NODES 32768
#define EMB 128
#define N_CODES 4096
#define NG 512

// output layout: c_logit[512], c_graph[512*128], s_graph[512*128],
// loss_c, loss_s, c_node[32768*128], s_node[32768*128]
#define OFF_LOGIT 0
#define OFF_CG    512
#define OFF_SG    (512 + 65536)
#define OFF_LC    (512 + 2 * 65536)
#define OFF_LS    (OFF_LC + 1)
#define OFF_CN    (OFF_LS + 1)
#define OFF_SN    (OFF_CN + N_NODES * EMB)

// device scratch (no allocations allowed)
__device__ float g_CT[128 * 8192];              // transposed concat codebook [k][n]
__device__ float g_halfc2[8192];                // 0.5*|c_n|^2
__device__ unsigned long long g_keyc[N_NODES];  // packed (dist,idx) argmin keys
__device__ unsigned long long g_keys[N_NODES];
__device__ int g_counts[NG];
__device__ double g_loss[2];

__device__ __forceinline__ void ffma2(unsigned long long& d, unsigned long long a,
                                      unsigned long long b) {
    asm volatile("fma.rn.f32x2 %0, %1, %2, %0;" : "+l"(d) : "l"(a), "l"(b));
}
__device__ __forceinline__ unsigned long long packf2(float a) {
    unsigned long long r; asm("mov.b64 %0, {%1, %1};" : "=l"(r) : "f"(a)); return r;
}
__device__ __forceinline__ float2 unpackf2(unsigned long long v) {
    float2 p; asm("mov.b64 {%0, %1}, %2;" : "=f"(p.x), "=f"(p.y) : "l"(v)); return p;
}
__device__ __forceinline__ unsigned int fkey(float f) {
    unsigned u = __float_as_uint(f);
    return (u & 0x80000000u) ? ~u : (u | 0x80000000u);
}

// ---------- init ----------
__global__ void init_kernel(float* __restrict__ out) {
    int i = blockIdx.x * blockDim.x + threadIdx.x;  // 65536 threads
    if (i < N_NODES) { g_keyc[i] = ~0ULL; g_keys[i] = ~0ULL; }
    if (i < NG) g_counts[i] = 0;
    if (i < 2) g_loss[i] = 0.0;
    out[OFF_CG + 2 * i] = 0.f;
    out[OFF_CG + 2 * i + 1] = 0.f;
}

// ---------- transpose concat codebook into g_CT[k][n] ----------
__global__ void transpose_kernel(const float* __restrict__ cbc, const float* __restrict__ cbs) {
    __shared__ float t[32][33];
    int bx = blockIdx.x, by = blockIdx.y;
    int tx = threadIdx.x, ty = threadIdx.y;  // (32,8)
    for (int yy = ty; yy < 32; yy += 8) {
        int n = bx * 32 + yy, k = by * 32 + tx;
        t[yy][tx] = (n < N_CODES) ? cbc[(size_t)n * EMB + k]
                                  : cbs[(size_t)(n - N_CODES) * EMB + k];
    }
    __syncthreads();
    for (int yy = ty; yy < 32; yy += 8) {
        int k = by * 32 + yy, n = bx * 32 + tx;
        g_CT[(size_t)k * 8192 + n] = t[tx][yy];
    }
}

// ---------- 0.5*|c|^2 ----------
__global__ void halfc2_kernel(const float* __restrict__ cbc, const float* __restrict__ cbs) {
    int w = blockIdx.x * 8 + (threadIdx.x >> 5);
    int lane = threadIdx.x & 31;
    const float* row = (w < N_CODES) ? (cbc + (size_t)w * EMB)
                                     : (cbs + (size_t)(w - N_CODES) * EMB);
    float4 v = ((const float4*)row)[lane];
    float s = v.x * v.x + v.y * v.y + v.z * v.z + v.w * v.w;
    for (int o = 16; o; o >>= 1) s += __shfl_xor_sync(0xffffffffu, s, o);
    if (lane == 0) g_halfc2[w] = 0.5f * s;
}

// ---------- main GEMM + argmin ----------
// grid 1024: mb = bid>>2 (128 nodes), nr = bid&3 (2048 codes = 16 chunks of 128)
// 256 threads, 8x8 micro-tile: tx = tid&15 spans n (8 each), ty = tid>>4 spans m (8 each)
#define SMEM_BYTES (65536 + 131072 + 1024 + 512 + 1024)

__global__ void __launch_bounds__(256, 1)
gemm_argmin_kernel(const float* __restrict__ nodef, const float* __restrict__ score) {
    extern __shared__ char smem[];
    float* As = (float*)smem;                       // [k][m] 64KB
    float* Bs = (float*)(smem + 65536);             // 2 x [k][128n] 128KB
    float* c2s = (float*)(smem + 65536 + 131072);   // 2 x 128
    float* gbuf = c2s + 256;                        // 128
    unsigned long long* bestk = (unsigned long long*)(gbuf + 128);  // 128

    const int tid = threadIdx.x;
    const int tx = tid & 15, ty = tid >> 4;   // ty in [0,15]
    const int m0 = ty * 8;
    const int mb = blockIdx.x >> 2;
    const int nr = blockIdx.x & 3;
    const int mbase = mb * 128;
    const int nbase = nr * 2048;
    const int cb = nbase >> 12;  // 0 = codebook_c half, 1 = codebook_s half

    // prologue: async-copy B chunk 0 + its half|c|^2 slice
    for (int s = 0; s < 16; s++) {
        int kk = (tid >> 5) + 8 * s, c4 = tid & 31;
        __pipeline_memcpy_async(Bs + kk * 128 + c4 * 4,
                                g_CT + (size_t)kk * 8192 + nbase + c4 * 4, 16);
    }
    if (tid < 32) __pipeline_memcpy_async(c2s + tid * 4, g_halfc2 + nbase + tid * 4, 16);
    __pipeline_commit();

    if (tid < 128) {
        bestk[tid] = ~0ULL;
        float s = score[mbase + tid];
        gbuf[tid] = cb ? (1.0f - 0.5f * s) : (0.5f + 0.5f * s);
    }
    // A load, transposed into [k][m]; each thread handles half of one row
    {
        int row = tid & 127, half = tid >> 7;
        const float4* Ar = (const float4*)(nodef + (size_t)(mbase + row) * EMB) + half * 16;
        for (int i = 0; i < 16; i++) {
            float4 v = Ar[i];
            int kk = (half * 16 + i) * 4;
            As[(kk + 0) * 128 + row] = v.x;
            As[(kk + 1) * 128 + row] = v.y;
            As[(kk + 2) * 128 + row] = v.z;
            As[(kk + 3) * 128 + row] = v.w;
        }
    }
    __syncthreads();

    unsigned long long acc[8][4];
    float4 af[2][2];
    unsigned long long bf[2][4];

    for (int ci = 0; ci < 16; ci++) {
        float* Bcur = Bs + (ci & 1) * 16384;
        const float* c2cur = c2s + (ci & 1) * 128;
        __pipeline_wait_prior(0);
        __syncthreads();
        if (ci + 1 < 16) {
            float* dst = Bs + ((ci + 1) & 1) * 16384;
            int nco = nbase + (ci + 1) * 128;
            for (int s = 0; s < 16; s++) {
                int kk = (tid >> 5) + 8 * s, c4 = tid & 31;
                __pipeline_memcpy_async(dst + kk * 128 + c4 * 4,
                                        g_CT + (size_t)kk * 8192 + nco + c4 * 4, 16);
            }
            if (tid < 32)
                __pipeline_memcpy_async(c2s + ((ci + 1) & 1) * 128 + tid * 4,
                                        g_halfc2 + nco + tid * 4, 16);
            __pipeline_commit();
        }

#pragma unroll
        for (int i = 0; i < 8; i++)
#pragma unroll
            for (int j = 0; j < 4; j++) acc[i][j] = 0ULL;

        {   // frag k=0
            const float4* Arow = (const float4*)(As + m0);
            af[0][0] = Arow[0]; af[0][1] = Arow[1];
            const unsigned long long* Brow = (const unsigned long long*)Bcur;
#pragma unroll
            for (int j = 0; j < 4; j++) bf[0][j] = Brow[tx + 16 * j];
        }

#pragma unroll 4
        for (int k = 0; k < 128; k++) {
            const int cur = k & 1, nxt = cur ^ 1;
            if (k < 127) {
                const float4* Arow = (const float4*)(As + (k + 1) * 128 + m0);
                af[nxt][0] = Arow[0]; af[nxt][1] = Arow[1];
                const unsigned long long* Brow =
                    (const unsigned long long*)(Bcur + (k + 1) * 128);
#pragma unroll
                for (int j = 0; j < 4; j++) bf[nxt][j] = Brow[tx + 16 * j];
            }
#pragma unroll
            for (int q = 0; q < 2; q++) {
                float4 a4 = af[cur][q];
                unsigned long long am;
                am = packf2(a4.x);
                ffma2(acc[q * 4 + 0][0], am, bf[cur][0]); ffma2(acc[q * 4 + 0][1], am, bf[cur][1]);
                ffma2(acc[q * 4 + 0][2], am, bf[cur][2]); ffma2(acc[q * 4 + 0][3], am, bf[cur][3]);
                am = packf2(a4.y);
                ffma2(acc[q * 4 + 1][0], am, bf[cur][0]); ffma2(acc[q * 4 + 1][1], am, bf[cur][1]);
                ffma2(acc[q * 4 + 1][2], am, bf[cur][2]); ffma2(acc[q * 4 + 1][3], am, bf[cur][3]);
                am = packf2(a4.z);
                ffma2(acc[q * 4 + 2][0], am, bf[cur][0]); ffma2(acc[q * 4 + 2][1], am, bf[cur][1]);
                ffma2(acc[q * 4 + 2][2], am, bf[cur][2]); ffma2(acc[q * 4 + 2][3], am, bf[cur][3]);
                am = packf2(a4.w);
                ffma2(acc[q * 4 + 3][0], am, bf[cur][0]); ffma2(acc[q * 4 + 3][1], am, bf[cur][1]);
                ffma2(acc[q * 4 + 3][2], am, bf[cur][2]); ffma2(acc[q * 4 + 3][3], am, bf[cur][3]);
            }
        }

        // epilogue: running argmin of (0.5|c|^2 - g*<x,c>)
        int cbBaseIdx = (nbase & 4095) + ci * 128;
#pragma unroll
        for (int mm = 0; mm < 8; mm++) {
            float g = gbuf[m0 + mm];
            float best = __int_as_float(0x7f800000);
            int bi = 0;
#pragma unroll
            for (int j = 0; j < 4; j++) {
                float2 p = unpackf2(acc[mm][j]);
                int nl = 2 * tx + 32 * j;
                float v0 = fmaf(-g, p.x, c2cur[nl]);
                float v1 = fmaf(-g, p.y, c2cur[nl + 1]);
                if (v0 < best) { best = v0; bi = nl; }
                if (v1 < best) { best = v1; bi = nl + 1; }
            }
            unsigned long long key =
                ((unsigned long long)fkey(best) << 32) | (unsigned)(cbBaseIdx + bi);
#pragma unroll
            for (int o = 8; o; o >>= 1) {
                unsigned long long other = __shfl_xor_sync(0xffffffffu, key, o, 16);
                if (other < key) key = other;
            }
            if (tx == 0 && key < bestk[m0 + mm]) bestk[m0 + mm] = key;
        }
    }
    __syncthreads();
    if (tid < 128) atomicMin((cb ? g_keys : g_keyc) + mbase + tid, bestk[tid]);
}

// ---------- per-node outputs + segment sums + commit losses ----------
__global__ void __launch_bounds__(128)
node_kernel(const float* __restrict__ nodef, const float* __restrict__ score,
            const int* __restrict__ batch,
            const float* __restrict__ cbc, const float* __restrict__ cbs,
            float* __restrict__ out) {
    __shared__ float s_sh[64];
    __shared__ int b_sh[64], ic_sh[64], is_sh[64];
    __shared__ double lred[8];
    const int tid = threadIdx.x;
    const int n0 = blockIdx.x * 64;
    if (tid < 64) {
        int n = n0 + tid;
        s_sh[tid] = score[n];
        b_sh[tid] = batch[n];
        ic_sh[tid] = (int)(g_keyc[n] & 0xffffffffULL);
        is_sh[tid] = (int)(g_keys[n] & 0xffffffffULL);
    }
    __syncthreads();
    float* csum = out + OFF_CG;
    float* ssum = out + OFF_SG;
    float* cn = out + OFF_CN;
    float* sn = out + OFF_SN;
    const int d = tid;
    float cacc = 0.f, sacc = 0.f;
    double lc = 0.0, ls = 0.0;
    int curg = b_sh[0], runlen = 0;
    for (int i = 0; i < 64; i++) {
        int n = n0 + i;
        int gidx = b_sh[i];
        if (gidx != curg) {
            atomicAdd(&csum[curg * EMB + d], cacc);
            atomicAdd(&ssum[curg * EMB + d], sacc);
            if (d == 0) atomicAdd(&g_counts[curg], runlen);
            cacc = 0.f; sacc = 0.f; runlen = 0; curg = gidx;
        }
        float x = nodef[(size_t)n * EMB + d];
        float s = s_sh[i];
        float qc = cbc[(size_t)ic_sh[i] * EMB + d];
        float qs = cbs[(size_t)is_sh[i] * EMB + d];
        float cv = x * s + qc;
        float sv = x * (1.f - s) + qs;
        cn[(size_t)n * EMB + d] = cv;
        sn[(size_t)n * EMB + d] = sv;
        float dc = qc - (0.5f + 0.5f * s) * x;
        float ds = qs - (1.0f - 0.5f * s) * x;
        lc += (double)(dc * dc);
        ls += (double)(ds * ds);
        cacc += cv; sacc += sv; runlen++;
    }
    atomicAdd(&csum[curg * EMB + d], cacc);
    atomicAdd(&ssum[curg * EMB + d], sacc);
    if (d == 0) atomicAdd(&g_counts[curg], runlen);
    for (int o = 16; o; o >>= 1) {
        lc += __shfl_xor_sync(0xffffffffu, lc, o);
        ls += __shfl_xor_sync(0xffffffffu, ls, o);
    }
    int w = tid >> 5, lane = tid & 31;
    if (lane == 0) { lred[w] = lc; lred[4 + w] = ls; }
    __syncthreads();
    if (tid == 0) {
        atomicAdd(&g_loss[0], lred[0] + lred[1] + lred[2] + lred[3]);
        atomicAdd(&g_loss[1], lred[4] + lred[5] + lred[6] + lred[7]);
    }
}

// ---------- finalize means + losses ----------
__global__ void finalize_kernel(float* __restrict__ out) {
    int g = blockIdx.x, d = threadIdx.x;
    float cnt = fmaxf((float)g_counts[g], 1.0f);
    out[OFF_CG + g * EMB + d] /= cnt;
    out[OFF_SG + g * EMB + d] /= cnt;
    if (g == 0 && d == 0) {
        out[OFF_LC] = (float)(g_loss[0] / ((double)N_NODES * (double)EMB));
        out[OFF_LS] = (float)(g_loss[1] / ((double)N_NODES * (double)EMB));
    }
}

// ---------- classifier head ----------
__global__ void __launch_bounds__(256)
classifier_kernel(const float* __restrict__ w1, const float* __restrict__ b1,
                  const float* __restrict__ gamma, const float* __restrict__ beta,
                  const float* __restrict__ rmean, const float* __restrict__ rvar,
                  const float* __restrict__ w2, const float* __restrict__ b2,
                  float* __restrict__ out) {
    __shared__ float cg_s[128];
    __shared__ float red[256];
    int g = blockIdx.x, j = threadIdx.x;
    if (j < 128) cg_s[j] = out[OFF_CG + g * EMB + j];
    __syncthreads();
    float acc = 0.f;
#pragma unroll 8
    for (int k = 0; k < 128; k++) acc = fmaf(cg_s[k], w1[k * 256 + j], acc);
    float h = acc + b1[j];
    h = (h - rmean[j]) * rsqrtf(rvar[j] + 1e-5f) * gamma[j] + beta[j];
    h = fmaxf(h, 0.f);
    red[j] = h * w2[j];
    __syncthreads();
    for (int o = 128; o; o >>= 1) {
        if (j < o) red[j] += red[j + o];
        __syncthreads();
    }
    if (j == 0) out[OFF_LOGIT + g] = red[0] + b2[0];
}

extern "C" void kernel_launch(void* const* d_in, const int* in_sizes, int n_in,
                              void* d_out, int out_size) {
    (void)in_sizes; (void)n_in; (void)out_size;
    const float* nodef = (const float*)d_in[0];
    const float* score = (const float*)d_in[1];
    const int* batch = (const int*)d_in[2];
    const float* cbc = (const float*)d_in[3];
    const float* cbs = (const float*)d_in[4];
    const float* w1 = (const float*)d_in[5];
    const float* b1 = (const float*)d_in[6];
    const float* gamma = (const float*)d_in[7];
    const float* beta = (const float*)d_in[8];
    const float* rmean = (const float*)d_in[9];
    const float* rvar = (const float*)d_in[10];
    const float* w2 = (const float*)d_in[11];
    const float* b2 = (const float*)d_in[12];
    float* out = (float*)d_out;

    cudaFuncSetAttribute(gemm_argmin_kernel,
                         cudaFuncAttributeMaxDynamicSharedMemorySize, SMEM_BYTES);

    init_kernel<<<256, 256>>>(out);
    transpose_kernel<<<dim3(256, 4), dim3(32, 8)>>>(cbc, cbs);
    halfc2_kernel<<<1024, 256>>>(cbc, cbs);
    gemm_argmin_kernel<<<1024, 256, SMEM_BYTES>>>(nodef, score);
    node_kernel<<<512, 128>>>(nodef, score, batch, cbc, cbs, out);
    finalize_kernel<<<NG, 128>>>(out);
    classifier_kernel<<<NG, 256>>>(w1, b1, gamma, beta, rmean, rvar, w2, b2, out);
}

// round 7
// speedup vs baseline: 2.0292x; 2.0292x over previous
#include <cuda_runtime.h>
#include <cuda_pipeline.h>
#include <cuda_bf16.h>
#include <cstdint>

#define N_NODES 32768
#define EMB 128
#define N_CODES 4096
#define NG 512

// output layout: c_logit[512], c_graph[512*128], s_graph[512*128],
// loss_c, loss_s, c_node[32768*128], s_node[32768*128]
#define OFF_LOGIT 0
#define OFF_CG    512
#define OFF_SG    (512 + 65536)
#define OFF_LC    (512 + 2 * 65536)
#define OFF_LS    (OFF_LC + 1)
#define OFF_CN    (OFF_LS + 1)
#define OFF_SN    (OFF_CN + N_NODES * EMB)

// device scratch (no allocations allowed)
__device__ __align__(16) __nv_bfloat16 g_Bhi[8192 * 128];  // bf16 hi codebook [n][k]
__device__ __align__(16) __nv_bfloat16 g_Blo[8192 * 128];  // bf16 lo codebook [n][k]
__device__ __align__(16) float g_halfc2[8192];             // 0.5*|c_n|^2 exact fp32
__device__ unsigned long long g_kc1[N_NODES], g_kc2[N_NODES];  // top-2 keys, codebook c
__device__ unsigned long long g_ks1[N_NODES], g_ks2[N_NODES];  // top-2 keys, codebook s
__device__ int g_idxc[N_NODES], g_idxs[N_NODES];               // final exact indices
__device__ int g_counts[NG];
__device__ double g_loss[2];

// ---------------- helpers ----------------
__device__ __forceinline__ unsigned int fkey(float f) {
    unsigned u = __float_as_uint(f);
    return (u & 0x80000000u) ? ~u : (u | 0x80000000u);  // order-preserving
}
__device__ __forceinline__ uint32_t smem_u32(const void* p) {
    uint32_t a;
    asm("{ .reg .u64 t; cvta.to.shared.u64 t, %1; cvt.u32.u64 %0, t; }" : "=r"(a) : "l"(p));
    return a;
}
// pack two floats to bf16x2: lo 16 bits = a, hi = b
__device__ __forceinline__ uint32_t pack_bf16x2(float a, float b) {
    uint32_t r;
    asm("cvt.rn.satfinite.bf16x2.f32 %0, %1, %2;" : "=r"(r) : "f"(b), "f"(a));
    return r;
}
__device__ __forceinline__ void split2(float2 v, uint32_t& h, uint32_t& l) {
    h = pack_bf16x2(v.x, v.y);
    float hx = __uint_as_float(h << 16);
    float hy = __uint_as_float(h & 0xffff0000u);
    l = pack_bf16x2(v.x - hx, v.y - hy);
}
__device__ __forceinline__ void mma_bf16(float* c, const uint32_t* a, uint32_t b0, uint32_t b1) {
    asm volatile(
        "mma.sync.aligned.m16n8k16.row.col.f32.bf16.bf16.f32 "
        "{%0,%1,%2,%3}, {%4,%5,%6,%7}, {%8,%9}, {%0,%1,%2,%3};"
        : "+f"(c[0]), "+f"(c[1]), "+f"(c[2]), "+f"(c[3])
        : "r"(a[0]), "r"(a[1]), "r"(a[2]), "r"(a[3]), "r"(b0), "r"(b1));
}
__device__ __forceinline__ void ldm4(uint32_t* r, uint32_t addr) {
    asm volatile("ldmatrix.sync.aligned.m8n8.x4.shared.b16 {%0,%1,%2,%3}, [%4];"
                 : "=r"(r[0]), "=r"(r[1]), "=r"(r[2]), "=r"(r[3]) : "r"(addr));
}
__device__ __forceinline__ void upd2(unsigned long long& b, unsigned long long& s,
                                     float d, unsigned idx) {
    unsigned long long k = ((unsigned long long)fkey(d) << 32) | idx;
    if (k < s) {
        if (k < b) { s = b; b = k; } else s = k;
    }
}
__device__ __forceinline__ void qmerge(unsigned long long& b, unsigned long long& s) {
#pragma unroll
    for (int off = 1; off <= 2; off <<= 1) {
        unsigned long long ob = __shfl_xor_sync(0xffffffffu, b, off);
        unsigned long long os = __shfl_xor_sync(0xffffffffu, s, off);
        if (ob < b) { s = (b < os) ? b : os; b = ob; }
        else if (ob < s) s = ob;
    }
}

// ---------- init ----------
__global__ void init_kernel(float* __restrict__ out) {
    int i = blockIdx.x * blockDim.x + threadIdx.x;  // 65536 threads
    if (i < NG) g_counts[i] = 0;
    if (i < 2) g_loss[i] = 0.0;
    out[OFF_CG + 2 * i] = 0.f;
    out[OFF_CG + 2 * i + 1] = 0.f;
}

// ---------- B prep: bf16 hi/lo split + 0.5|c|^2 ----------
__global__ void bprep_kernel(const float* __restrict__ cbc, const float* __restrict__ cbs) {
    int row = blockIdx.x * 8 + (threadIdx.x >> 5);
    int lane = threadIdx.x & 31;
    const float* src = (row < N_CODES) ? cbc + (size_t)row * EMB
                                       : cbs + (size_t)(row - N_CODES) * EMB;
    float4 v = ((const float4*)src)[lane];
    float ss = v.x * v.x + v.y * v.y + v.z * v.z + v.w * v.w;
    uint32_t h0, l0, h1, l1;
    split2(make_float2(v.x, v.y), h0, l0);
    split2(make_float2(v.z, v.w), h1, l1);
    uint32_t* hid = (uint32_t*)g_Bhi;
    uint32_t* lod = (uint32_t*)g_Blo;
    hid[row * 64 + lane * 2] = h0; hid[row * 64 + lane * 2 + 1] = h1;
    lod[row * 64 + lane * 2] = l0; lod[row * 64 + lane * 2 + 1] = l1;
    for (int o = 16; o; o >>= 1) ss += __shfl_xor_sync(0xffffffffu, ss, o);
    if (lane == 0) g_halfc2[row] = 0.5f * ss;
}

// ---------- tensor GEMM + top-2 argmin ----------
// grid 256 CTAs x 256 threads; each CTA owns 128 m-rows, scans 8192 codes
// in 128 chunks of 64. B double-buffered bf16 hi/lo in smem, ldmatrix loads.
#define BSTRIDE 272
#define BUFB 17408                       // 64 rows * 272B
#define SMEM_GEMM (4 * BUFB + 512)       // 2x(hi+lo) + 2x256B halfc2

__device__ __forceinline__ void prefetch(char* smem, int ci, int tid) {
    int buf = ci & 1;
    int nb = ci * 64;
    char* hid = smem + buf * BUFB;
    char* lod = smem + 2 * BUFB + buf * BUFB;
#pragma unroll
    for (int i = 0; i < 4; i++) {
        int idx = tid + i * 256;                 // 0..1023
        int row = idx >> 4, seg = idx & 15;
        __pipeline_memcpy_async(hid + row * BSTRIDE + seg * 16,
                                (const char*)g_Bhi + (size_t)(nb + row) * 256 + seg * 16, 16);
        __pipeline_memcpy_async(lod + row * BSTRIDE + seg * 16,
                                (const char*)g_Blo + (size_t)(nb + row) * 256 + seg * 16, 16);
    }
    if (tid < 16)
        __pipeline_memcpy_async(smem + 4 * BUFB + (ci & 1) * 256 + tid * 16,
                                (const char*)g_halfc2 + (size_t)nb * 4 + tid * 16, 16);
}

template <int CB>
__device__ __forceinline__ void half_loop(
    char* smem, uint32_t smemBase, uint32_t rp, int tid, int c,
    const uint32_t (&Ahi)[8][4], const uint32_t (&Alo)[8][4],
    float g0, float g1,
    unsigned long long& b0, unsigned long long& s0k,
    unsigned long long& b1, unsigned long long& s1k) {
    for (int i = 0; i < 64; i++) {
        int ci = CB * 64 + i;
        __pipeline_wait_prior(0);
        __syncthreads();
        if (ci + 1 < 128) { prefetch(smem, ci + 1, tid); __pipeline_commit(); }
        int buf = ci & 1;
        uint32_t hiB = smemBase + buf * BUFB + rp;
        uint32_t loB = smemBase + 2 * BUFB + buf * BUFB + rp;
        const float* h2 = (const float*)(smem + 4 * BUFB + buf * 256);
        float acc[8][4];
#pragma unroll
        for (int t = 0; t < 8; t++)
#pragma unroll
            for (int j = 0; j < 4; j++) acc[t][j] = 0.f;
#pragma unroll
        for (int kt = 0; kt < 8; kt++) {
            uint32_t BH[4][4], BL[4][4];
#pragma unroll
            for (int j = 0; j < 4; j++) {
                ldm4(BH[j], hiB + j * (16 * BSTRIDE) + kt * 32);
                ldm4(BL[j], loB + j * (16 * BSTRIDE) + kt * 32);
            }
#pragma unroll
            for (int t = 0; t < 8; t++) {
                uint32_t b0h = BH[t >> 1][(t & 1) * 2], b1h = BH[t >> 1][(t & 1) * 2 + 1];
                uint32_t b0l = BL[t >> 1][(t & 1) * 2], b1l = BL[t >> 1][(t & 1) * 2 + 1];
                mma_bf16(acc[t], Ahi[kt], b0h, b1h);
                mma_bf16(acc[t], Ahi[kt], b0l, b1l);
                mma_bf16(acc[t], Alo[kt], b0h, b1h);
            }
        }
#pragma unroll
        for (int t = 0; t < 8; t++) {
            float2 hh = *(const float2*)(h2 + t * 8 + 2 * c);
            unsigned nb = (unsigned)(ci * 64 + t * 8 + 2 * c);
            upd2(b0, s0k, fmaf(-g0, acc[t][0], hh.x), nb);
            upd2(b0, s0k, fmaf(-g0, acc[t][1], hh.y), nb + 1);
            upd2(b1, s1k, fmaf(-g1, acc[t][2], hh.x), nb);
            upd2(b1, s1k, fmaf(-g1, acc[t][3], hh.y), nb + 1);
        }
    }
}

__global__ void __launch_bounds__(256, 1)
gemm_argmin_kernel(const float* __restrict__ nodef, const float* __restrict__ score) {
    extern __shared__ char smem[];
    const int tid = threadIdx.x;
    const int w = tid >> 5, lane = tid & 31;
    const int gp = lane >> 2, c = lane & 3;
    const int mbase = blockIdx.x * 128;
    const int r0 = mbase + w * 16 + gp, r1 = r0 + 8;

    prefetch(smem, 0, tid);
    __pipeline_commit();

    // A fragments (bf16 hi/lo), loaded once per CTA
    uint32_t Ahi[8][4], Alo[8][4];
#pragma unroll
    for (int kt = 0; kt < 8; kt++) {
        const float* p0 = nodef + (size_t)r0 * EMB + kt * 16 + 2 * c;
        const float* p1 = nodef + (size_t)r1 * EMB + kt * 16 + 2 * c;
        split2(*(const float2*)p0, Ahi[kt][0], Alo[kt][0]);
        split2(*(const float2*)p1, Ahi[kt][1], Alo[kt][1]);
        split2(*(const float2*)(p0 + 8), Ahi[kt][2], Alo[kt][2]);
        split2(*(const float2*)(p1 + 8), Ahi[kt][3], Alo[kt][3]);
    }

    float s0 = score[r0], s1 = score[r1];
    float gc0 = 0.5f + 0.5f * s0, gc1 = 0.5f + 0.5f * s1;
    float gs0 = 1.0f - 0.5f * s0, gs1 = 1.0f - 0.5f * s1;

    // ldmatrix per-thread row address part
    int g8 = lane >> 3, rr = lane & 7;
    uint32_t rp = (uint32_t)((8 * (g8 >> 1) + rr) * BSTRIDE + (g8 & 1) * 16);
    uint32_t smemBase = smem_u32(smem);

    unsigned long long bC0 = ~0ULL, sC0 = ~0ULL, bC1 = ~0ULL, sC1 = ~0ULL;
    unsigned long long bS0 = ~0ULL, sS0 = ~0ULL, bS1 = ~0ULL, sS1 = ~0ULL;

    half_loop<0>(smem, smemBase, rp, tid, c, Ahi, Alo, gc0, gc1, bC0, sC0, bC1, sC1);
    half_loop<1>(smem, smemBase, rp, tid, c, Ahi, Alo, gs0, gs1, bS0, sS0, bS1, sS1);

    qmerge(bC0, sC0); qmerge(bC1, sC1);
    qmerge(bS0, sS0); qmerge(bS1, sS1);
    if ((lane & 3) == 0) {
        g_kc1[r0] = bC0; g_kc2[r0] = sC0;
        g_kc1[r1] = bC1; g_kc2[r1] = sC1;
        g_ks1[r0] = bS0; g_ks2[r0] = sS0;
        g_ks1[r1] = bS1; g_ks2[r1] = sS1;
    }
}

// ---------- exact fp32 rescore of top-2 candidates ----------
__global__ void __launch_bounds__(64)
rescore_kernel(const float* __restrict__ nodef, const float* __restrict__ score,
               const float* __restrict__ cbc, const float* __restrict__ cbs) {
    int n = blockIdx.x;
    int wid = threadIdx.x >> 5, lane = threadIdx.x & 31;
    unsigned long long k1 = wid ? g_ks1[n] : g_kc1[n];
    unsigned long long k2 = wid ? g_ks2[n] : g_kc2[n];
    unsigned i1 = (unsigned)k1, i2 = (unsigned)k2;   // global col 0..8191
    unsigned base = wid ? 4096u : 0u;
    const float* cb = wid ? cbs : cbc;
    const float* c1p = cb + (size_t)(i1 - base) * EMB;
    const float* c2p = cb + (size_t)(i2 - base) * EMB;
    float4 x = ((const float4*)(nodef + (size_t)n * EMB))[lane];
    float4 a = ((const float4*)c1p)[lane];
    float4 b = ((const float4*)c2p)[lane];
    float d1 = x.x * a.x + x.y * a.y + x.z * a.z + x.w * a.w;
    float d2 = x.x * b.x + x.y * b.y + x.z * b.z + x.w * b.w;
    for (int o = 16; o; o >>= 1) {
        d1 += __shfl_xor_sync(0xffffffffu, d1, o);
        d2 += __shfl_xor_sync(0xffffffffu, d2, o);
    }
    if (lane == 0) {
        float s = score[n];
        float g = wid ? (1.0f - 0.5f * s) : (0.5f + 0.5f * s);
        float D1 = fmaf(-g, d1, g_halfc2[i1]);
        float D2 = fmaf(-g, d2, g_halfc2[i2]);
        int winner = (D2 < D1 || (D2 == D1 && i2 < i1)) ? (int)(i2 - base) : (int)(i1 - base);
        if (wid) g_idxs[n] = winner; else g_idxc[n] = winner;
    }
}

// ---------- per-node outputs + segment sums + commit losses ----------
__global__ void __launch_bounds__(128)
node_kernel(const float* __restrict__ nodef, const float* __restrict__ score,
            const int* __restrict__ batch,
            const float* __restrict__ cbc, const float* __restrict__ cbs,
            float* __restrict__ out) {
    __shared__ float s_sh[64];
    __shared__ int b_sh[64], ic_sh[64], is_sh[64];
    __shared__ double lred[8];
    const int tid = threadIdx.x;
    const int n0 = blockIdx.x * 64;
    if (tid < 64) {
        int n = n0 + tid;
        s_sh[tid] = score[n];
        b_sh[tid] = batch[n];
        ic_sh[tid] = g_idxc[n];
        is_sh[tid] = g_idxs[n];
    }
    __syncthreads();
    float* csum = out + OFF_CG;
    float* ssum = out + OFF_SG;
    float* cn = out + OFF_CN;
    float* sn = out + OFF_SN;
    const int d = tid;
    float cacc = 0.f, sacc = 0.f;
    double lc = 0.0, ls = 0.0;
    int curg = b_sh[0], runlen = 0;
    for (int i = 0; i < 64; i++) {
        int n = n0 + i;
        int gidx = b_sh[i];
        if (gidx != curg) {
            atomicAdd(&csum[curg * EMB + d], cacc);
            atomicAdd(&ssum[curg * EMB + d], sacc);
            if (d == 0) atomicAdd(&g_counts[curg], runlen);
            cacc = 0.f; sacc = 0.f; runlen = 0; curg = gidx;
        }
        float x = nodef[(size_t)n * EMB + d];
        float s = s_sh[i];
        float qc = cbc[(size_t)ic_sh[i] * EMB + d];
        float qs = cbs[(size_t)is_sh[i] * EMB + d];
        float cv = x * s + qc;
        float sv = x * (1.f - s) + qs;
        cn[(size_t)n * EMB + d] = cv;
        sn[(size_t)n * EMB + d] = sv;
        float dc = qc - (0.5f + 0.5f * s) * x;
        float ds = qs - (1.0f - 0.5f * s) * x;
        lc += (double)(dc * dc);
        ls += (double)(ds * ds);
        cacc += cv; sacc += sv; runlen++;
    }
    atomicAdd(&csum[curg * EMB + d], cacc);
    atomicAdd(&ssum[curg * EMB + d], sacc);
    if (d == 0) atomicAdd(&g_counts[curg], runlen);
    for (int o = 16; o; o >>= 1) {
        lc += __shfl_xor_sync(0xffffffffu, lc, o);
        ls += __shfl_xor_sync(0xffffffffu, ls, o);
    }
    int w = tid >> 5, lane = tid & 31;
    if (lane == 0) { lred[w] = lc; lred[4 + w] = ls; }
    __syncthreads();
    if (tid == 0) {
        atomicAdd(&g_loss[0], lred[0] + lred[1] + lred[2] + lred[3]);
        atomicAdd(&g_loss[1], lred[4] + lred[5] + lred[6] + lred[7]);
    }
}

// ---------- finalize means + losses ----------
__global__ void finalize_kernel(float* __restrict__ out) {
    int g = blockIdx.x, d = threadIdx.x;
    float cnt = fmaxf((float)g_counts[g], 1.0f);
    out[OFF_CG + g * EMB + d] /= cnt;
    out[OFF_SG + g * EMB + d] /= cnt;
    if (g == 0 && d == 0) {
        out[OFF_LC] = (float)(g_loss[0] / ((double)N_NODES * (double)EMB));
        out[OFF_LS] = (float)(g_loss[1] / ((double)N_NODES * (double)EMB));
    }
}

// ---------- classifier head ----------
__global__ void __launch_bounds__(256)
classifier_kernel(const float* __restrict__ w1, const float* __restrict__ b1,
                  const float* __restrict__ gamma, const float* __restrict__ beta,
                  const float* __restrict__ rmean, const float* __restrict__ rvar,
                  const float* __restrict__ w2, const float* __restrict__ b2,
                  float* __restrict__ out) {
    __shared__ float cg_s[128];
    __shared__ float red[256];
    int g = blockIdx.x, j = threadIdx.x;
    if (j < 128) cg_s[j] = out[OFF_CG + g * EMB + j];
    __syncthreads();
    float acc = 0.f;
#pragma unroll 8
    for (int k = 0; k < 128; k++) acc = fmaf(cg_s[k], w1[k * 256 + j], acc);
    float h = acc + b1[j];
    h = (h - rmean[j]) * rsqrtf(rvar[j] + 1e-5f) * gamma[j] + beta[j];
    h = fmaxf(h, 0.f);
    red[j] = h * w2[j];
    __syncthreads();
    for (int o = 128; o; o >>= 1) {
        if (j < o) red[j] += red[j + o];
        __syncthreads();
    }
    if (j == 0) out[OFF_LOGIT + g] = red[0] + b2[0];
}

extern "C" void kernel_launch(void* const* d_in, const int* in_sizes, int n_in,
                              void* d_out, int out_size) {
    (void)in_sizes; (void)n_in; (void)out_size;
    const float* nodef = (const float*)d_in[0];
    const float* score = (const float*)d_in[1];
    const int* batch = (const int*)d_in[2];
    const float* cbc = (const float*)d_in[3];
    const float* cbs = (const float*)d_in[4];
    const float* w1 = (const float*)d_in[5];
    const float* b1 = (const float*)d_in[6];
    const float* gamma = (const float*)d_in[7];
    const float* beta = (const float*)d_in[8];
    const float* rmean = (const float*)d_in[9];
    const float* rvar = (const float*)d_in[10];
    const float* w2 = (const float*)d_in[11];
    const float* b2 = (const float*)d_in[12];
    float* out = (float*)d_out;

    cudaFuncSetAttribute(gemm_argmin_kernel,
                         cudaFuncAttributeMaxDynamicSharedMemorySize, SMEM_GEMM);

    init_kernel<<<256, 256>>>(out);
    bprep_kernel<<<1024, 256>>>(cbc, cbs);
    gemm_argmin_kernel<<<256, 256, SMEM_GEMM>>>(nodef, score);
    rescore_kernel<<<N_NODES, 64>>>(nodef, score, cbc, cbs);
    node_kernel<<<512, 128>>>(nodef, score, batch, cbc, cbs, out);
    finalize_kernel<<<NG, 128>>>(out);
    classifier_kernel<<<NG, 256>>>(w1, b1, gamma, beta, rmean, rvar, w2, b2, out);
}

// round 9
// speedup vs baseline: 4.3439x; 2.1407x over previous
#include <cuda_runtime.h>
#include <cuda_pipeline.h>
#include <cuda_bf16.h>
#include <cstdint>

#define N_NODES 32768
#define EMB 128
#define N_CODES 4096
#define NG 512

// output layout: c_logit[512], c_graph[512*128], s_graph[512*128],
// loss_c, loss_s, c_node[32768*128], s_node[32768*128]
#define OFF_LOGIT 0
#define OFF_CG    512
#define OFF_SG    (512 + 65536)
#define OFF_LC    (512 + 2 * 65536)
#define OFF_LS    (OFF_LC + 1)
#define OFF_CN    (OFF_LS + 1)
#define OFF_SN    (OFF_CN + N_NODES * EMB)

// device scratch (no allocations allowed)
__device__ __align__(16) __nv_bfloat16 g_Bhi[8192 * 128];  // bf16 codebook [n][k]
__device__ __align__(16) float g_halfc2[8192];             // 0.5*|c_n|^2 exact fp32
__device__ int g_candc[N_NODES * 12];                      // 12 candidates/node (cb c)
__device__ int g_cands[N_NODES * 12];                      // 12 candidates/node (cb s)
__device__ int g_idxc[N_NODES], g_idxs[N_NODES];           // final exact indices
__device__ int g_counts[NG];
__device__ double g_loss[2];

// ---------------- helpers ----------------
__device__ __forceinline__ uint32_t smem_u32(const void* p) {
    uint32_t a;
    asm("{ .reg .u64 t; cvta.to.shared.u64 t, %1; cvt.u32.u64 %0, t; }" : "=r"(a) : "l"(p));
    return a;
}
__device__ __forceinline__ uint32_t pack_bf16x2(float a, float b) {
    uint32_t r;
    asm("cvt.rn.satfinite.bf16x2.f32 %0, %1, %2;" : "=r"(r) : "f"(b), "f"(a));
    return r;
}
__device__ __forceinline__ void mma_bf16(float* c, const uint32_t* a, uint32_t b0, uint32_t b1) {
    asm volatile(
        "mma.sync.aligned.m16n8k16.row.col.f32.bf16.bf16.f32 "
        "{%0,%1,%2,%3}, {%4,%5,%6,%7}, {%8,%9}, {%0,%1,%2,%3};"
        : "+f"(c[0]), "+f"(c[1]), "+f"(c[2]), "+f"(c[3])
        : "r"(a[0]), "r"(a[1]), "r"(a[2]), "r"(a[3]), "r"(b0), "r"(b1));
}
__device__ __forceinline__ void ldm4(uint32_t* r, uint32_t addr) {
    asm volatile("ldmatrix.sync.aligned.m8n8.x4.shared.b16 {%0,%1,%2,%3}, [%4];"
                 : "=r"(r[0]), "=r"(r[1]), "=r"(r[2]), "=r"(r[3]) : "r"(addr));
}
// top-3 (smallest) tracker, approx phase (tie-break irrelevant: exact rescore later)
__device__ __forceinline__ void upd3(float d, int idx, float (&bd)[3], int (&bi)[3]) {
    if (d < bd[2]) {
        if (d < bd[1]) {
            if (d < bd[0]) {
                bd[2] = bd[1]; bi[2] = bi[1];
                bd[1] = bd[0]; bi[1] = bi[0];
                bd[0] = d;     bi[0] = idx;
            } else {
                bd[2] = bd[1]; bi[2] = bi[1];
                bd[1] = d;     bi[1] = idx;
            }
        } else { bd[2] = d; bi[2] = idx; }
    }
}

// ---------- init ----------
__global__ void init_kernel(float* __restrict__ out) {
    int i = blockIdx.x * blockDim.x + threadIdx.x;  // 65536 threads
    if (i < NG) g_counts[i] = 0;
    if (i < 2) g_loss[i] = 0.0;
    out[OFF_CG + 2 * i] = 0.f;
    out[OFF_CG + 2 * i + 1] = 0.f;
}

// ---------- B prep: bf16 + 0.5|c|^2 ----------
__global__ void bprep_kernel(const float* __restrict__ cbc, const float* __restrict__ cbs) {
    int row = blockIdx.x * 8 + (threadIdx.x >> 5);
    int lane = threadIdx.x & 31;
    const float* src = (row < N_CODES) ? cbc + (size_t)row * EMB
                                       : cbs + (size_t)(row - N_CODES) * EMB;
    float4 v = ((const float4*)src)[lane];
    float ss = v.x * v.x + v.y * v.y + v.z * v.z + v.w * v.w;
    uint32_t* hid = (uint32_t*)g_Bhi;
    hid[row * 64 + lane * 2] = pack_bf16x2(v.x, v.y);
    hid[row * 64 + lane * 2 + 1] = pack_bf16x2(v.z, v.w);
    for (int o = 16; o; o >>= 1) ss += __shfl_xor_sync(0xffffffffu, ss, o);
    if (lane == 0) g_halfc2[row] = 0.5f * ss;
}

// ---------- tensor GEMM (1-pass bf16) + per-thread top-3 ----------
// grid 256 CTAs x 256 threads; each CTA owns 128 m-rows, scans 8192 codes
// in 128 chunks of 64. B double-buffered bf16 in smem, ldmatrix loads.
#define BSTRIDE 272
#define BUFB 17408                       // 64 rows * 272B
#define SMEM_GEMM (2 * BUFB + 512)       // 2x hi + 2x256B halfc2

__device__ __forceinline__ void prefetch(char* smem, int ci, int tid) {
    int buf = ci & 1;
    int nb = ci * 64;
    char* hid = smem + buf * BUFB;
#pragma unroll
    for (int i = 0; i < 4; i++) {
        int idx = tid + i * 256;                 // 0..1023
        int row = idx >> 4, seg = idx & 15;
        __pipeline_memcpy_async(hid + row * BSTRIDE + seg * 16,
                                (const char*)g_Bhi + (size_t)(nb + row) * 256 + seg * 16, 16);
    }
    if (tid < 16)
        __pipeline_memcpy_async(smem + 2 * BUFB + (ci & 1) * 256 + tid * 16,
                                (const char*)g_halfc2 + (size_t)nb * 4 + tid * 16, 16);
}

template <int CB>
__device__ __forceinline__ void half_loop(
    char* smem, uint32_t smemBase, uint32_t rp, int tid, int c,
    const uint32_t (&Ahi)[8][4], float g0, float g1,
    float (&d0)[3], int (&i0)[3], float (&d1)[3], int (&i1)[3]) {
    for (int i = 0; i < 64; i++) {
        int ci = CB * 64 + i;
        __pipeline_wait_prior(0);
        __syncthreads();
        if (ci + 1 < 128) { prefetch(smem, ci + 1, tid); __pipeline_commit(); }
        int buf = ci & 1;
        uint32_t hiB = smemBase + buf * BUFB + rp;
        const float* h2 = (const float*)(smem + 2 * BUFB + buf * 256);
        float acc[8][4];
#pragma unroll
        for (int t = 0; t < 8; t++)
#pragma unroll
            for (int j = 0; j < 4; j++) acc[t][j] = 0.f;
#pragma unroll
        for (int kt = 0; kt < 8; kt++) {
            uint32_t BH[4][4];
#pragma unroll
            for (int j = 0; j < 4; j++)
                ldm4(BH[j], hiB + j * (16 * BSTRIDE) + kt * 32);
#pragma unroll
            for (int t = 0; t < 8; t++)
                mma_bf16(acc[t], Ahi[kt],
                         BH[t >> 1][(t & 1) * 2], BH[t >> 1][(t & 1) * 2 + 1]);
        }
#pragma unroll
        for (int t = 0; t < 8; t++) {
            float2 hh = *(const float2*)(h2 + t * 8 + 2 * c);
            int col = i * 64 + t * 8 + 2 * c;       // local codebook index 0..4095
            upd3(fmaf(-g0, acc[t][0], hh.x), col, d0, i0);
            upd3(fmaf(-g0, acc[t][1], hh.y), col + 1, d0, i0);
            upd3(fmaf(-g1, acc[t][2], hh.x), col, d1, i1);
            upd3(fmaf(-g1, acc[t][3], hh.y), col + 1, d1, i1);
        }
    }
}

__global__ void __launch_bounds__(256)
gemm_argmin_kernel(const float* __restrict__ nodef, const float* __restrict__ score) {
    extern __shared__ char smem[];
    const int tid = threadIdx.x;
    const int w = tid >> 5, lane = tid & 31;
    const int gp = lane >> 2, c = lane & 3;
    const int mbase = blockIdx.x * 128;
    const int r0 = mbase + w * 16 + gp, r1 = r0 + 8;

    prefetch(smem, 0, tid);
    __pipeline_commit();

    // A fragments (bf16), loaded once per CTA
    uint32_t Ahi[8][4];
#pragma unroll
    for (int kt = 0; kt < 8; kt++) {
        const float* p0 = nodef + (size_t)r0 * EMB + kt * 16 + 2 * c;
        const float* p1 = nodef + (size_t)r1 * EMB + kt * 16 + 2 * c;
        float2 v;
        v = *(const float2*)p0;       Ahi[kt][0] = pack_bf16x2(v.x, v.y);
        v = *(const float2*)p1;       Ahi[kt][1] = pack_bf16x2(v.x, v.y);
        v = *(const float2*)(p0 + 8); Ahi[kt][2] = pack_bf16x2(v.x, v.y);
        v = *(const float2*)(p1 + 8); Ahi[kt][3] = pack_bf16x2(v.x, v.y);
    }

    float s0 = score[r0], s1 = score[r1];
    float gc0 = 0.5f + 0.5f * s0, gc1 = 0.5f + 0.5f * s1;
    float gs0 = 1.0f - 0.5f * s0, gs1 = 1.0f - 0.5f * s1;

    // ldmatrix per-thread row address part
    int g8 = lane >> 3, rr = lane & 7;
    uint32_t rp = (uint32_t)((8 * (g8 >> 1) + rr) * BSTRIDE + (g8 & 1) * 16);
    uint32_t smemBase = smem_u32(smem);

    const float INF = __int_as_float(0x7f800000);
    float dC0[3] = {INF, INF, INF}, dC1[3] = {INF, INF, INF};
    float dS0[3] = {INF, INF, INF}, dS1[3] = {INF, INF, INF};
    int iC0[3] = {0, 0, 0}, iC1[3] = {0, 0, 0}, iS0[3] = {0, 0, 0}, iS1[3] = {0, 0, 0};

    half_loop<0>(smem, smemBase, rp, tid, c, Ahi, gc0, gc1, dC0, iC0, dC1, iC1);
    half_loop<1>(smem, smemBase, rp, tid, c, Ahi, gs0, gs1, dS0, iS0, dS1, iS1);

    // each thread writes its 3 candidates per row per codebook (12 total per row/cb)
    int b0 = r0 * 12 + c * 3, b1 = r1 * 12 + c * 3;
#pragma unroll
    for (int j = 0; j < 3; j++) {
        g_candc[b0 + j] = iC0[j];
        g_candc[b1 + j] = iC1[j];
        g_cands[b0 + j] = iS0[j];
        g_cands[b1 + j] = iS1[j];
    }
}

// ---------- exact fp32 rescore of 12 candidates ----------
__global__ void __launch_bounds__(64)
rescore_kernel(const float* __restrict__ nodef, const float* __restrict__ score,
               const float* __restrict__ cbc, const float* __restrict__ cbs) {
    int n = blockIdx.x;
    int wid = threadIdx.x >> 5, lane = threadIdx.x & 31;
    const int* cand = (wid ? g_cands : g_candc) + n * 12;
    const float* cb = wid ? cbs : cbc;
    const float* h2 = g_halfc2 + (wid ? 4096 : 0);
    float4 x = ((const float4*)(nodef + (size_t)n * EMB))[lane];
    float s = score[n];
    float g = wid ? (1.0f - 0.5f * s) : (0.5f + 0.5f * s);
    float bestd = __int_as_float(0x7f800000);
    int besti = 0x7fffffff;
#pragma unroll
    for (int j = 0; j < 12; j++) {
        int idx = cand[j];
        float4 a = ((const float4*)(cb + (size_t)idx * EMB))[lane];
        float d = x.x * a.x + x.y * a.y + x.z * a.z + x.w * a.w;
        for (int o = 16; o; o >>= 1) d += __shfl_xor_sync(0xffffffffu, d, o);
        float D = fmaf(-g, d, h2[idx]);
        if (D < bestd || (D == bestd && idx < besti)) { bestd = D; besti = idx; }
    }
    if (lane == 0) {
        if (wid) g_idxs[n] = besti; else g_idxc[n] = besti;
    }
}

// ---------- per-node outputs + segment sums + commit losses ----------
__global__ void __launch_bounds__(128)
node_kernel(const float* __restrict__ nodef, const float* __restrict__ score,
            const int* __restrict__ batch,
            const float* __restrict__ cbc, const float* __restrict__ cbs,
            float* __restrict__ out) {
    __shared__ float s_sh[64];
    __shared__ int b_sh[64], ic_sh[64], is_sh[64];
    __shared__ double lred[8];
    const int tid = threadIdx.x;
    const int n0 = blockIdx.x * 64;
    if (tid < 64) {
        int n = n0 + tid;
        s_sh[tid] = score[n];
        b_sh[tid] = batch[n];
        ic_sh[tid] = g_idxc[n];
        is_sh[tid] = g_idxs[n];
    }
    __syncthreads();
    float* csum = out + OFF_CG;
    float* ssum = out + OFF_SG;
    float* cn = out + OFF_CN;
    float* sn = out + OFF_SN;
    const int d = tid;
    float cacc = 0.f, sacc = 0.f;
    double lc = 0.0, ls = 0.0;
    int curg = b_sh[0], runlen = 0;
    for (int i = 0; i < 64; i++) {
        int n = n0 + i;
        int gidx = b_sh[i];
        if (gidx != curg) {
            atomicAdd(&csum[curg * EMB + d], cacc);
            atomicAdd(&ssum[curg * EMB + d], sacc);
            if (d == 0) atomicAdd(&g_counts[curg], runlen);
            cacc = 0.f; sacc = 0.f; runlen = 0; curg = gidx;
        }
        float x = nodef[(size_t)n * EMB + d];
        float s = s_sh[i];
        float qc = cbc[(size_t)ic_sh[i] * EMB + d];
        float qs = cbs[(size_t)is_sh[i] * EMB + d];
        float cv = x * s + qc;
        float sv = x * (1.f - s) + qs;
        cn[(size_t)n * EMB + d] = cv;
        sn[(size_t)n * EMB + d] = sv;
        float dc = qc - (0.5f + 0.5f * s) * x;
        float ds = qs - (1.0f - 0.5f * s) * x;
        lc += (double)(dc * dc);
        ls += (double)(ds * ds);
        cacc += cv; sacc += sv; runlen++;
    }
    atomicAdd(&csum[curg * EMB + d], cacc);
    atomicAdd(&ssum[curg * EMB + d], sacc);
    if (d == 0) atomicAdd(&g_counts[curg], runlen);
    for (int o = 16; o; o >>= 1) {
        lc += __shfl_xor_sync(0xffffffffu, lc, o);
        ls += __shfl_xor_sync(0xffffffffu, ls, o);
    }
    int w = tid >> 5, lane = tid & 31;
    if (lane == 0) { lred[w] = lc; lred[4 + w] = ls; }
    __syncthreads();
    if (tid == 0) {
        atomicAdd(&g_loss[0], lred[0] + lred[1] + lred[2] + lred[3]);
        atomicAdd(&g_loss[1], lred[4] + lred[5] + lred[6] + lred[7]);
    }
}

// ---------- finalize means + losses ----------
__global__ void finalize_kernel(float* __restrict__ out) {
    int g = blockIdx.x, d = threadIdx.x;
    float cnt = fmaxf((float)g_counts[g], 1.0f);
    out[OFF_CG + g * EMB + d] /= cnt;
    out[OFF_SG + g * EMB + d] /= cnt;
    if (g == 0 && d == 0) {
        out[OFF_LC] = (float)(g_loss[0] / ((double)N_NODES * (double)EMB));
        out[OFF_LS] = (float)(g_loss[1] / ((double)N_NODES * (double)EMB));
    }
}

// ---------- classifier head ----------
__global__ void __launch_bounds__(256)
classifier_kernel(const float* __restrict__ w1, const float* __restrict__ b1,
                  const float* __restrict__ gamma, const float* __restrict__ beta,
                  const float* __restrict__ rmean, const float* __restrict__ rvar,
                  const float* __restrict__ w2, const float* __restrict__ b2,
                  float* __restrict__ out) {
    __shared__ float cg_s[128];
    __shared__ float red[256];
    int g = blockIdx.x, j = threadIdx.x;
    if (j < 128) cg_s[j] = out[OFF_CG + g * EMB + j];
    __syncthreads();
    float acc = 0.f;
#pragma unroll 8
    for (int k = 0; k < 128; k++) acc = fmaf(cg_s[k], w1[k * 256 + j], acc);
    float h = acc + b1[j];
    h = (h - rmean[j]) * rsqrtf(rvar[j] + 1e-5f) * gamma[j] + beta[j];
    h = fmaxf(h, 0.f);
    red[j] = h * w2[j];
    __syncthreads();
    for (int o = 128; o; o >>= 1) {
        if (j < o) red[j] += red[j + o];
        __syncthreads();
    }
    if (j == 0) out[OFF_LOGIT + g] = red[0] + b2[0];
}

extern "C" void kernel_launch(void* const* d_in, const int* in_sizes, int n_in,
                              void* d_out, int out_size) {
    (void)in_sizes; (void)n_in; (void)out_size;
    const float* nodef = (const float*)d_in[0];
    const float* score = (const float*)d_in[1];
    const int* batch = (const int*)d_in[2];
    const float* cbc = (const float*)d_in[3];
    const float* cbs = (const float*)d_in[4];
    const float* w1 = (const float*)d_in[5];
    const float* b1 = (const float*)d_in[6];
    const float* gamma = (const float*)d_in[7];
    const float* beta = (const float*)d_in[8];
    const float* rmean = (const float*)d_in[9];
    const float* rvar = (const float*)d_in[10];
    const float* w2 = (const float*)d_in[11];
    const float* b2 = (const float*)d_in[12];
    float* out = (float*)d_out;

    cudaFuncSetAttribute(gemm_argmin_kernel,
                         cudaFuncAttributeMaxDynamicSharedMemorySize, SMEM_GEMM);

    init_kernel<<<256, 256>>>(out);
    bprep_kernel<<<1024, 256>>>(cbc, cbs);
    gemm_argmin_kernel<<<256, 256, SMEM_GEMM>>>(nodef, score);
    rescore_kernel<<<N_NODES, 64>>>(nodef, score, cbc, cbs);
    node_kernel<<<512, 128>>>(nodef, score, batch, cbc, cbs, out);
    finalize_kernel<<<NG, 128>>>(out);
    classifier_kernel<<<NG, 256>>>(w1, b1, gamma, beta, rmean, rvar, w2, b2, out);
}